// round 4
// baseline (speedup 1.0000x reference)
#include <cuda_runtime.h>
#include <cuda_bf16.h>

#define MAXN 100000
#define MAXE 1700000
#define FDIM 64

// Scratch — __device__ globals, referenced DIRECTLY in kernels.
// kernel_launch contains ONLY kernel launches (graph-capture safe).
__device__ int   g_is64;            // 1 if edge_index is int64, 0 if int32
__device__ int   g_cnt[MAXN];
__device__ int   g_off[MAXN + 1];
__device__ int   g_cursor[MAXN];
__device__ int   g_srcs[MAXE];
__device__ float g_dinv[MAXN];
__device__ float g_H1[(size_t)MAXN * FDIM];
__device__ float g_agg1[(size_t)MAXN * FDIM];
__device__ float g_H2[(size_t)MAXN * FDIM];

// ---------------------------------------------------------------------------
// Edge-index dtype detection: for genuine int64 (values < 1e5) every high
// 32-bit word is zero; for int32 data the "high word" is the next random
// index (nonzero w.p. ~1 - 1e-5). Checks 64 words -> certain in practice.
// ---------------------------------------------------------------------------
__global__ void detect_dtype_kernel(const unsigned int* __restrict__ raw,
                                    int n_words) {
    if (threadIdx.x == 0 && blockIdx.x == 0) {
        int nz = 0;
        int lim = n_words < 64 ? n_words : 64;
        for (int i = 0; i < lim; i++)
            if (raw[2 * i + 1] != 0u) nz++;
        g_is64 = (nz == 0) ? 1 : 0;
    }
}

__device__ __forceinline__ int edge_at(const void* ei, int is64, size_t idx) {
    if (is64) return (int)((const long long*)ei)[idx];
    return ((const int*)ei)[idx];
}

// ---------------------------------------------------------------------------
// CSR build
// ---------------------------------------------------------------------------
__global__ void zero_cnt_kernel(int M) {
    int i = blockIdx.x * blockDim.x + threadIdx.x;
    if (i < M) g_cnt[i] = 0;
}

__global__ void count_kernel(const void* __restrict__ ei, int E) {
    int e = blockIdx.x * blockDim.x + threadIdx.x;
    if (e < E) {
        int is64 = g_is64;
        int c = edge_at(ei, is64, (size_t)E + e);  // target node
        atomicAdd(&g_cnt[c], 1);
    }
}

// Single-block exclusive scan over M counts. Also emits cursor copy and
// dinv = rsqrt(cnt+1) (self-loop included).
__global__ void scan_kernel(int M) {
    __shared__ int ssum[1024];
    const int tid = threadIdx.x;
    const int per = (M + 1023) / 1024;
    const int start = tid * per;
    const int end = min(start + per, M);

    int s = 0;
    for (int i = start; i < end; i++) s += g_cnt[i];
    ssum[tid] = s;
    __syncthreads();

    for (int d = 1; d < 1024; d <<= 1) {
        int v = (tid >= d) ? ssum[tid - d] : 0;
        __syncthreads();
        ssum[tid] += v;
        __syncthreads();
    }
    int run = (tid == 0) ? 0 : ssum[tid - 1];

    for (int i = start; i < end; i++) {
        g_off[i] = run;
        g_cursor[i] = run;
        g_dinv[i] = rsqrtf((float)(g_cnt[i] + 1));
        run += g_cnt[i];
    }
    if (end == M) g_off[M] = run;
}

__global__ void fill_kernel(const void* __restrict__ ei, int E) {
    int e = blockIdx.x * blockDim.x + threadIdx.x;
    if (e < E) {
        int is64 = g_is64;
        int r = edge_at(ei, is64, (size_t)e);           // source
        int c = edge_at(ei, is64, (size_t)E + e);       // target
        int pos = atomicAdd(&g_cursor[c], 1);
        g_srcs[pos] = r;
    }
}

// ---------------------------------------------------------------------------
// Tiled fp32 GEMM: H = act(X) @ W. Epilogue fuses self-loop + bias:
// AGG = bias + H * dinv^2.   LAYER2 selects internal buffers + input ReLU.
// Block: 256 threads -> 64x64 tile; thread = 4x4 register tile.
// ---------------------------------------------------------------------------
template <int K, bool LAYER2>
__global__ void gcn_gemm_kernel(const float* __restrict__ Xin,
                                const float* __restrict__ W,
                                const float* __restrict__ bias,
                                float* __restrict__ AGGout, int M) {
    const float* X   = LAYER2 ? g_agg1 : Xin;
    float*       H   = LAYER2 ? g_H2   : g_H1;
    float*       AGG = LAYER2 ? AGGout : g_agg1;

    constexpr int KT = 64;
    __shared__ float Ws[KT][64];
    __shared__ float xs[64][68];  // padded: conflict-free

    const int tid = threadIdx.x;
    const int tx = tid & 15;
    const int ty = tid >> 4;
    const int row0 = blockIdx.x * 64;

    float acc[4][4];
#pragma unroll
    for (int r = 0; r < 4; r++)
#pragma unroll
        for (int c = 0; c < 4; c++) acc[r][c] = 0.0f;

    for (int k0 = 0; k0 < K; k0 += KT) {
#pragma unroll
        for (int i = tid; i < KT * 64; i += 256) {
            int kk = i >> 6, cc = i & 63;
            Ws[kk][cc] = W[(size_t)(k0 + kk) * 64 + cc];
        }
#pragma unroll
        for (int i = tid; i < 64 * (KT / 4); i += 256) {
            int r = i >> 4;
            int j = i & 15;
            int row = row0 + r;
            float4 v = make_float4(0.f, 0.f, 0.f, 0.f);
            if (row < M)
                v = *(const float4*)&X[(size_t)row * K + k0 + j * 4];
            if (LAYER2) {  // ReLU on layer-1 aggregate
                v.x = fmaxf(v.x, 0.f); v.y = fmaxf(v.y, 0.f);
                v.z = fmaxf(v.z, 0.f); v.w = fmaxf(v.w, 0.f);
            }
            xs[r][j * 4 + 0] = v.x; xs[r][j * 4 + 1] = v.y;
            xs[r][j * 4 + 2] = v.z; xs[r][j * 4 + 3] = v.w;
        }
        __syncthreads();

#pragma unroll 8
        for (int k = 0; k < KT; k++) {
            float4 w = *(const float4*)&Ws[k][tx * 4];
#pragma unroll
            for (int r = 0; r < 4; r++) {
                float xv = xs[ty * 4 + r][k];
                acc[r][0] += xv * w.x;
                acc[r][1] += xv * w.y;
                acc[r][2] += xv * w.z;
                acc[r][3] += xv * w.w;
            }
        }
        __syncthreads();
    }

    float4 bv = *(const float4*)&bias[tx * 4];
#pragma unroll
    for (int r = 0; r < 4; r++) {
        int row = row0 + ty * 4 + r;
        if (row < M) {
            float d = g_dinv[row];
            float d2 = d * d;
            float4 h = make_float4(acc[r][0], acc[r][1], acc[r][2], acc[r][3]);
            *(float4*)&H[(size_t)row * 64 + tx * 4] = h;
            float4 a = make_float4(bv.x + h.x * d2, bv.y + h.y * d2,
                                   bv.z + h.z * d2, bv.w + h.w * d2);
            *(float4*)&AGG[(size_t)row * 64 + tx * 4] = a;
        }
    }
}

// ---------------------------------------------------------------------------
// CSR gather: agg[n] += dinv[n] * sum_{src in N(n)} dinv[src]*H[src]
// 16 threads per node, one float4 channel slice each. No atomics.
// ---------------------------------------------------------------------------
template <bool LAYER2>
__global__ void gather_kernel(float* __restrict__ AGGout, int M) {
    const float* H   = LAYER2 ? g_H2   : g_H1;
    float*       agg = LAYER2 ? AGGout : g_agg1;

    long long gid = (long long)blockIdx.x * blockDim.x + threadIdx.x;
    int n = (int)(gid >> 4);
    if (n >= M) return;
    int lane = (int)(gid & 15);

    int s = g_off[n], e = g_off[n + 1];
    float ax = 0.f, ay = 0.f, az = 0.f, aw = 0.f;
    for (int j = s; j < e; j++) {
        int r = g_srcs[j];
        float w = g_dinv[r];
        float4 h = *(const float4*)&H[(size_t)r * 64 + lane * 4];
        ax += w * h.x; ay += w * h.y; az += w * h.z; aw += w * h.w;
    }
    float dn = g_dinv[n];
    size_t base = (size_t)n * 64 + lane * 4;
    float4 self = *(const float4*)&agg[base];
    self.x += dn * ax; self.y += dn * ay;
    self.z += dn * az; self.w += dn * aw;
    *(float4*)&agg[base] = self;
}

// ---------------------------------------------------------------------------
extern "C" void kernel_launch(void* const* d_in, const int* in_sizes, int n_in,
                              void* d_out, int out_size) {
    const float* x  = (const float*)d_in[0];
    const void*  ei = d_in[1];
    const float* W1 = (const float*)d_in[2];
    const float* b1 = (const float*)d_in[3];
    const float* W2 = (const float*)d_in[4];
    const float* b2 = (const float*)d_in[5];
    float*       out = (float*)d_out;

    const int M = in_sizes[0] / 128;   // 100000
    const int E = in_sizes[1] / 2;     // 1600000

    const int T = 256;
    // 0. detect edge dtype (int32 vs int64)
    detect_dtype_kernel<<<1, 32>>>((const unsigned int*)ei, E);

    // 1. CSR build + normalization
    zero_cnt_kernel<<<(M + T - 1) / T, T>>>(M);
    count_kernel<<<(E + T - 1) / T, T>>>(ei, E);
    scan_kernel<<<1, 1024>>>(M);
    fill_kernel<<<(E + T - 1) / T, T>>>(ei, E);

    // 2. layer 1
    gcn_gemm_kernel<128, false><<<(M + 63) / 64, T>>>(x, W1, b1, nullptr, M);
    gather_kernel<false><<<(int)(((long long)M * 16 + T - 1) / T), T>>>(nullptr, M);

    // 3. layer 2 (writes d_out)
    gcn_gemm_kernel<64, true><<<(M + 63) / 64, T>>>(nullptr, W2, b2, out, M);
    gather_kernel<true><<<(int)(((long long)M * 16 + T - 1) / T), T>>>(out, M);
}

// round 5
// speedup vs baseline: 1.9933x; 1.9933x over previous
#include <cuda_runtime.h>
#include <cuda_bf16.h>

#define MAXN 100000
#define MAXE 1700000
#define FDIM 64
#define NB_MAX ((MAXN + 255) / 256)   // 391

// Scratch — __device__ globals, referenced DIRECTLY in kernels.
__device__ int   g_is64;            // 1 if edge_index is int64, 0 if int32
__device__ int   g_cnt[MAXN];
__device__ int   g_off[MAXN + 1];
__device__ int   g_cursor[MAXN];
__device__ int   g_srcs[MAXE];
__device__ int   g_blockoff[NB_MAX];
__device__ float g_dinv[MAXN];
__device__ float g_H1[(size_t)MAXN * FDIM];
__device__ float g_agg1[(size_t)MAXN * FDIM];
__device__ float g_H2[(size_t)MAXN * FDIM];

// ---------------------------------------------------------------------------
// Edge-index dtype detection (int64 vs int32, see R4 notes).
// ---------------------------------------------------------------------------
__global__ void detect_dtype_kernel(const unsigned int* __restrict__ raw,
                                    int n_words) {
    if (threadIdx.x == 0 && blockIdx.x == 0) {
        int nz = 0;
        int lim = n_words < 64 ? n_words : 64;
        for (int i = 0; i < lim; i++)
            if (raw[2 * i + 1] != 0u) nz++;
        g_is64 = (nz == 0) ? 1 : 0;
    }
}

__device__ __forceinline__ int edge_at(const void* ei, int is64, size_t idx) {
    if (is64) return (int)((const long long*)ei)[idx];
    return ((const int*)ei)[idx];
}

// ---------------------------------------------------------------------------
// CSR build
// ---------------------------------------------------------------------------
__global__ void zero_cnt_kernel(int M) {
    int i = blockIdx.x * blockDim.x + threadIdx.x;
    if (i < M) g_cnt[i] = 0;
}

__global__ void count_kernel(const void* __restrict__ ei, int E) {
    int e = blockIdx.x * blockDim.x + threadIdx.x;
    if (e < E) {
        int is64 = g_is64;
        int c = edge_at(ei, is64, (size_t)E + e);  // target node
        atomicAdd(&g_cnt[c], 1);
    }
}

// --- 3-phase grid-wide exclusive scan of g_cnt -> g_off ---
// Phase A: per-block (256 elems) reduction -> g_blocksum
__global__ void scan_a_kernel(int M) {
    __shared__ int sh[256];
    int tid = threadIdx.x;
    int i = blockIdx.x * 256 + tid;
    int v = (i < M) ? g_cnt[i] : 0;
    sh[tid] = v;
    __syncthreads();
#pragma unroll
    for (int d = 128; d > 0; d >>= 1) {
        if (tid < d) sh[tid] += sh[tid + d];
        __syncthreads();
    }
    if (tid == 0) g_blockoff[blockIdx.x] = sh[0];  // raw sums for now
}

// Phase B: single block exclusive-scans NB block sums in place; writes total.
__global__ void scan_b_kernel(int NB, int M) {
    __shared__ int sh[1024];
    int tid = threadIdx.x;
    int v = (tid < NB) ? g_blockoff[tid] : 0;
    sh[tid] = v;
    __syncthreads();
    for (int d = 1; d < 1024; d <<= 1) {
        int t = (tid >= d) ? sh[tid - d] : 0;
        __syncthreads();
        sh[tid] += t;
        __syncthreads();
    }
    if (tid < NB) g_blockoff[tid] = sh[tid] - v;   // exclusive
    if (tid == NB - 1) g_off[M] = sh[tid];         // total edges
}

// Phase C: block-local exclusive scan + block offset; emits off/cursor/dinv.
__global__ void scan_c_kernel(int M) {
    __shared__ int sh[256];
    int tid = threadIdx.x;
    int i = blockIdx.x * 256 + tid;
    int v = (i < M) ? g_cnt[i] : 0;
    sh[tid] = v;
    __syncthreads();
    for (int d = 1; d < 256; d <<= 1) {
        int t = (tid >= d) ? sh[tid - d] : 0;
        __syncthreads();
        sh[tid] += t;
        __syncthreads();
    }
    if (i < M) {
        int pos = g_blockoff[blockIdx.x] + sh[tid] - v;  // exclusive
        g_off[i] = pos;
        g_cursor[i] = pos;
        g_dinv[i] = rsqrtf((float)(v + 1));
    }
}

__global__ void fill_kernel(const void* __restrict__ ei, int E) {
    int e = blockIdx.x * blockDim.x + threadIdx.x;
    if (e < E) {
        int is64 = g_is64;
        int r = edge_at(ei, is64, (size_t)e);           // source
        int c = edge_at(ei, is64, (size_t)E + e);       // target
        int pos = atomicAdd(&g_cursor[c], 1);
        g_srcs[pos] = r;
    }
}

// ---------------------------------------------------------------------------
// Tiled fp32 GEMM: H = act(X) @ W. Epilogue fuses self-loop + bias:
// AGG = bias + H * dinv^2.   LAYER2 selects internal buffers + input ReLU.
// ---------------------------------------------------------------------------
template <int K, bool LAYER2>
__global__ void gcn_gemm_kernel(const float* __restrict__ Xin,
                                const float* __restrict__ W,
                                const float* __restrict__ bias,
                                float* __restrict__ AGGout, int M) {
    const float* X   = LAYER2 ? g_agg1 : Xin;
    float*       H   = LAYER2 ? g_H2   : g_H1;
    float*       AGG = LAYER2 ? AGGout : g_agg1;

    constexpr int KT = 64;
    __shared__ float Ws[KT][64];
    __shared__ float xs[64][68];  // padded: conflict-free

    const int tid = threadIdx.x;
    const int tx = tid & 15;
    const int ty = tid >> 4;
    const int row0 = blockIdx.x * 64;

    float acc[4][4];
#pragma unroll
    for (int r = 0; r < 4; r++)
#pragma unroll
        for (int c = 0; c < 4; c++) acc[r][c] = 0.0f;

    for (int k0 = 0; k0 < K; k0 += KT) {
#pragma unroll
        for (int i = tid; i < KT * 64; i += 256) {
            int kk = i >> 6, cc = i & 63;
            Ws[kk][cc] = W[(size_t)(k0 + kk) * 64 + cc];
        }
#pragma unroll
        for (int i = tid; i < 64 * (KT / 4); i += 256) {
            int r = i >> 4;
            int j = i & 15;
            int row = row0 + r;
            float4 v = make_float4(0.f, 0.f, 0.f, 0.f);
            if (row < M)
                v = *(const float4*)&X[(size_t)row * K + k0 + j * 4];
            if (LAYER2) {  // ReLU on layer-1 aggregate
                v.x = fmaxf(v.x, 0.f); v.y = fmaxf(v.y, 0.f);
                v.z = fmaxf(v.z, 0.f); v.w = fmaxf(v.w, 0.f);
            }
            xs[r][j * 4 + 0] = v.x; xs[r][j * 4 + 1] = v.y;
            xs[r][j * 4 + 2] = v.z; xs[r][j * 4 + 3] = v.w;
        }
        __syncthreads();

#pragma unroll 8
        for (int k = 0; k < KT; k++) {
            float4 w = *(const float4*)&Ws[k][tx * 4];
#pragma unroll
            for (int r = 0; r < 4; r++) {
                float xv = xs[ty * 4 + r][k];
                acc[r][0] += xv * w.x;
                acc[r][1] += xv * w.y;
                acc[r][2] += xv * w.z;
                acc[r][3] += xv * w.w;
            }
        }
        __syncthreads();
    }

    float4 bv = *(const float4*)&bias[tx * 4];
#pragma unroll
    for (int r = 0; r < 4; r++) {
        int row = row0 + ty * 4 + r;
        if (row < M) {
            float d = g_dinv[row];
            float d2 = d * d;
            float4 h = make_float4(acc[r][0], acc[r][1], acc[r][2], acc[r][3]);
            *(float4*)&H[(size_t)row * 64 + tx * 4] = h;
            float4 a = make_float4(bv.x + h.x * d2, bv.y + h.y * d2,
                                   bv.z + h.z * d2, bv.w + h.w * d2);
            *(float4*)&AGG[(size_t)row * 64 + tx * 4] = a;
        }
    }
}

// ---------------------------------------------------------------------------
// CSR gather: agg[n] += dinv[n] * sum_{src in N(n)} dinv[src]*H[src]
// 16 threads per node, one float4 channel slice each. No atomics.
// ---------------------------------------------------------------------------
template <bool LAYER2>
__global__ void gather_kernel(float* __restrict__ AGGout, int M) {
    const float* H   = LAYER2 ? g_H2   : g_H1;
    float*       agg = LAYER2 ? AGGout : g_agg1;

    long long gid = (long long)blockIdx.x * blockDim.x + threadIdx.x;
    int n = (int)(gid >> 4);
    if (n >= M) return;
    int lane = (int)(gid & 15);

    int s = g_off[n], e = g_off[n + 1];
    float ax = 0.f, ay = 0.f, az = 0.f, aw = 0.f;
    for (int j = s; j < e; j++) {
        int r = g_srcs[j];
        float w = g_dinv[r];
        float4 h = *(const float4*)&H[(size_t)r * 64 + lane * 4];
        ax += w * h.x; ay += w * h.y; az += w * h.z; aw += w * h.w;
    }
    float dn = g_dinv[n];
    size_t base = (size_t)n * 64 + lane * 4;
    float4 self = *(const float4*)&agg[base];
    self.x += dn * ax; self.y += dn * ay;
    self.z += dn * az; self.w += dn * aw;
    *(float4*)&agg[base] = self;
}

// ---------------------------------------------------------------------------
extern "C" void kernel_launch(void* const* d_in, const int* in_sizes, int n_in,
                              void* d_out, int out_size) {
    const float* x  = (const float*)d_in[0];
    const void*  ei = d_in[1];
    const float* W1 = (const float*)d_in[2];
    const float* b1 = (const float*)d_in[3];
    const float* W2 = (const float*)d_in[4];
    const float* b2 = (const float*)d_in[5];
    float*       out = (float*)d_out;

    const int M = in_sizes[0] / 128;   // 100000
    const int E = in_sizes[1] / 2;     // 1600000
    const int NB = (M + 255) / 256;    // scan blocks

    const int T = 256;
    // 0. detect edge dtype (int32 vs int64)
    detect_dtype_kernel<<<1, 32>>>((const unsigned int*)ei, E);

    // 1. CSR build + normalization (3-phase grid-wide scan)
    zero_cnt_kernel<<<(M + T - 1) / T, T>>>(M);
    count_kernel<<<(E + T - 1) / T, T>>>(ei, E);
    scan_a_kernel<<<NB, 256>>>(M);
    scan_b_kernel<<<1, 1024>>>(NB, M);
    scan_c_kernel<<<NB, 256>>>(M);
    fill_kernel<<<(E + T - 1) / T, T>>>(ei, E);

    // 2. layer 1
    gcn_gemm_kernel<128, false><<<(M + 63) / 64, T>>>(x, W1, b1, nullptr, M);
    gather_kernel<false><<<(int)(((long long)M * 16 + T - 1) / T), T>>>(nullptr, M);

    // 3. layer 2 (writes d_out)
    gcn_gemm_kernel<64, true><<<(M + 63) / 64, T>>>(nullptr, W2, b2, out, M);
    gather_kernel<true><<<(int)(((long long)M * 16 + T - 1) / T), T>>>(out, M);
}

// round 6
// speedup vs baseline: 2.2553x; 1.1314x over previous
#include <cuda_runtime.h>
#include <cuda_bf16.h>

#define MAXN 100000
#define MAXE 1700000
#define FDIM 64
#define NB_MAX ((MAXN + 255) / 256)   // 391

// Scratch — __device__ globals, referenced DIRECTLY in kernels.
__device__ int   g_is64;            // 1 if edge_index is int64, 0 if int32
__device__ int   g_cnt[MAXN];
__device__ int   g_off[MAXN + 1];
__device__ int   g_cursor[MAXN];
__device__ int   g_srcs[MAXE];
__device__ int   g_blockoff[NB_MAX];
__device__ float g_dinv[MAXN];
__device__ float g_Hs1[(size_t)MAXN * FDIM];   // dinv-scaled hidden, layer 1
__device__ float g_agg1[(size_t)MAXN * FDIM];
__device__ float g_Hs2[(size_t)MAXN * FDIM];   // dinv-scaled hidden, layer 2

// ---------------------------------------------------------------------------
// init: detect edge dtype (block 0, thread 0) + zero g_cnt (whole grid).
// int64 data (values < 1e5) has all-zero high words; int32 data doesn't.
// ---------------------------------------------------------------------------
__global__ void init_kernel(const unsigned int* __restrict__ raw, int M, int E) {
    int i = blockIdx.x * blockDim.x + threadIdx.x;
    if (i < M) g_cnt[i] = 0;
    if (i == 0) {
        int nz = 0;
        int lim = E < 64 ? E : 64;
        for (int k = 0; k < lim; k++)
            if (raw[2 * k + 1] != 0u) nz++;
        g_is64 = (nz == 0) ? 1 : 0;
    }
}

__device__ __forceinline__ int edge_at(const void* ei, int is64, size_t idx) {
    if (is64) return (int)((const long long*)ei)[idx];
    return ((const int*)ei)[idx];
}

__global__ void count_kernel(const void* __restrict__ ei, int E) {
    int e = blockIdx.x * blockDim.x + threadIdx.x;
    if (e < E) {
        int is64 = g_is64;
        int c = edge_at(ei, is64, (size_t)E + e);  // target node
        atomicAdd(&g_cnt[c], 1);
    }
}

// dinv from counts (independent of the scan -> lets GEMM1 run early)
__global__ void dinv_kernel(int M) {
    int i = blockIdx.x * blockDim.x + threadIdx.x;
    if (i < M) g_dinv[i] = rsqrtf((float)(g_cnt[i] + 1));
}

// --- 3-phase grid-wide exclusive scan of g_cnt -> g_off ---
__global__ void scan_a_kernel(int M) {
    __shared__ int sh[256];
    int tid = threadIdx.x;
    int i = blockIdx.x * 256 + tid;
    int v = (i < M) ? g_cnt[i] : 0;
    sh[tid] = v;
    __syncthreads();
#pragma unroll
    for (int d = 128; d > 0; d >>= 1) {
        if (tid < d) sh[tid] += sh[tid + d];
        __syncthreads();
    }
    if (tid == 0) g_blockoff[blockIdx.x] = sh[0];
}

__global__ void scan_b_kernel(int NB, int M) {
    __shared__ int sh[1024];
    int tid = threadIdx.x;
    int v = (tid < NB) ? g_blockoff[tid] : 0;
    sh[tid] = v;
    __syncthreads();
    for (int d = 1; d < 1024; d <<= 1) {
        int t = (tid >= d) ? sh[tid - d] : 0;
        __syncthreads();
        sh[tid] += t;
        __syncthreads();
    }
    if (tid < NB) g_blockoff[tid] = sh[tid] - v;   // exclusive
    if (tid == NB - 1) g_off[M] = sh[tid];
}

__global__ void scan_c_kernel(int M) {
    __shared__ int sh[256];
    int tid = threadIdx.x;
    int i = blockIdx.x * 256 + tid;
    int v = (i < M) ? g_cnt[i] : 0;
    sh[tid] = v;
    __syncthreads();
    for (int d = 1; d < 256; d <<= 1) {
        int t = (tid >= d) ? sh[tid - d] : 0;
        __syncthreads();
        sh[tid] += t;
        __syncthreads();
    }
    if (i < M) {
        int pos = g_blockoff[blockIdx.x] + sh[tid] - v;  // exclusive
        g_off[i] = pos;
        g_cursor[i] = pos;
    }
}

__global__ void fill_kernel(const void* __restrict__ ei, int E) {
    int e = blockIdx.x * blockDim.x + threadIdx.x;
    if (e < E) {
        int is64 = g_is64;
        int r = edge_at(ei, is64, (size_t)e);           // source
        int c = edge_at(ei, is64, (size_t)E + e);       // target
        int pos = atomicAdd(&g_cursor[c], 1);
        g_srcs[pos] = r;
    }
}

// ---------------------------------------------------------------------------
// GEMM: Hs = dinv .* (act(X) @ W);  AGGself = bias + dinv .* Hs
// 256 threads -> 128x64 tile; thread = 8x4; k-major transposed X tile.
// ---------------------------------------------------------------------------
template <int K, bool LAYER2>
__global__ void gcn_gemm_kernel(const float* __restrict__ Xin,
                                const float* __restrict__ W,
                                const float* __restrict__ bias,
                                float* __restrict__ AGGout, int M) {
    const float* X   = LAYER2 ? g_agg1 : Xin;
    float*       Hs  = LAYER2 ? g_Hs2  : g_Hs1;
    float*       AGG = LAYER2 ? AGGout : g_agg1;

    constexpr int KT = 32;
    constexpr int XS = 132;              // xsT row stride (floats)
    __shared__ float Ws[KT][64];         // 8 KB
    __shared__ float xsT[KT][XS];        // 16.9 KB, k-major

    const int tid = threadIdx.x;
    const int tx = tid & 15;             // col group: cols tx*4..+3
    const int ty = tid >> 4;             // row group: rows ty*8..+7
    const int row0 = blockIdx.x * 128;

    float acc[8][4];
#pragma unroll
    for (int r = 0; r < 8; r++)
#pragma unroll
        for (int c = 0; c < 4; c++) acc[r][c] = 0.0f;

    for (int k0 = 0; k0 < K; k0 += KT) {
        // W tile: 32x64 = 512 float4, 2 per thread
#pragma unroll
        for (int i = tid; i < KT * 16; i += 256) {
            int kk = i >> 4, cc = (i & 15) * 4;
            *(float4*)&Ws[kk][cc] = *(const float4*)&W[(size_t)(k0 + kk) * 64 + cc];
        }
        // X tile, transposed store: 128 rows x 32 k = 1024 float4, 4 per thread
#pragma unroll
        for (int i = tid; i < 128 * 8; i += 256) {
            int r = i >> 3;              // row 0..127
            int j = i & 7;               // k group
            int row = row0 + r;
            float4 v = make_float4(0.f, 0.f, 0.f, 0.f);
            if (row < M)
                v = *(const float4*)&X[(size_t)row * K + k0 + j * 4];
            if (LAYER2) {
                v.x = fmaxf(v.x, 0.f); v.y = fmaxf(v.y, 0.f);
                v.z = fmaxf(v.z, 0.f); v.w = fmaxf(v.w, 0.f);
            }
            xsT[j * 4 + 0][r] = v.x;
            xsT[j * 4 + 1][r] = v.y;
            xsT[j * 4 + 2][r] = v.z;
            xsT[j * 4 + 3][r] = v.w;
        }
        __syncthreads();

#pragma unroll 4
        for (int k = 0; k < KT; k++) {
            float4 w  = *(const float4*)&Ws[k][tx * 4];
            float4 xa = *(const float4*)&xsT[k][ty * 8];
            float4 xb = *(const float4*)&xsT[k][ty * 8 + 4];
            const float xv[8] = {xa.x, xa.y, xa.z, xa.w, xb.x, xb.y, xb.z, xb.w};
#pragma unroll
            for (int r = 0; r < 8; r++) {
                acc[r][0] += xv[r] * w.x;
                acc[r][1] += xv[r] * w.y;
                acc[r][2] += xv[r] * w.z;
                acc[r][3] += xv[r] * w.w;
            }
        }
        __syncthreads();
    }

    float4 bv = *(const float4*)&bias[tx * 4];
#pragma unroll
    for (int r = 0; r < 8; r++) {
        int row = row0 + ty * 8 + r;
        if (row < M) {
            float d = g_dinv[row];
            float4 h = make_float4(acc[r][0] * d, acc[r][1] * d,
                                   acc[r][2] * d, acc[r][3] * d);
            *(float4*)&Hs[(size_t)row * 64 + tx * 4] = h;
            float4 a = make_float4(bv.x + h.x * d, bv.y + h.y * d,
                                   bv.z + h.z * d, bv.w + h.w * d);
            *(float4*)&AGG[(size_t)row * 64 + tx * 4] = a;
        }
    }
}

// ---------------------------------------------------------------------------
// CSR gather: agg[n] += dinv[n] * sum_{src in N(n)} Hs[src]
// 16 threads per node, one float4 channel slice each. 2 loads/edge-lane.
// ---------------------------------------------------------------------------
template <bool LAYER2>
__global__ void gather_kernel(float* __restrict__ AGGout, int M) {
    const float* Hs  = LAYER2 ? g_Hs2  : g_Hs1;
    float*       agg = LAYER2 ? AGGout : g_agg1;

    long long gid = (long long)blockIdx.x * blockDim.x + threadIdx.x;
    int n = (int)(gid >> 4);
    if (n >= M) return;
    int lane = (int)(gid & 15);

    int s = g_off[n], e = g_off[n + 1];
    float ax = 0.f, ay = 0.f, az = 0.f, aw = 0.f;
#pragma unroll 4
    for (int j = s; j < e; j++) {
        int r = g_srcs[j];
        float4 h = *(const float4*)&Hs[(size_t)r * 64 + lane * 4];
        ax += h.x; ay += h.y; az += h.z; aw += h.w;
    }
    float dn = g_dinv[n];
    size_t base = (size_t)n * 64 + lane * 4;
    float4 self = *(const float4*)&agg[base];
    self.x += dn * ax; self.y += dn * ay;
    self.z += dn * az; self.w += dn * aw;
    *(float4*)&agg[base] = self;
}

// ---------------------------------------------------------------------------
extern "C" void kernel_launch(void* const* d_in, const int* in_sizes, int n_in,
                              void* d_out, int out_size) {
    const float* x  = (const float*)d_in[0];
    const void*  ei = d_in[1];
    const float* W1 = (const float*)d_in[2];
    const float* b1 = (const float*)d_in[3];
    const float* W2 = (const float*)d_in[4];
    const float* b2 = (const float*)d_in[5];
    float*       out = (float*)d_out;

    const int M = in_sizes[0] / 128;   // 100000
    const int E = in_sizes[1] / 2;     // 1600000
    const int NB = (M + 255) / 256;

    const int T = 256;
    // 1: dtype detect + zero counts
    init_kernel<<<(M + T - 1) / T, T>>>((const unsigned int*)ei, M, E);
    // 2: degree counts
    count_kernel<<<(E + T - 1) / T, T>>>(ei, E);
    // 3: dinv (only needs counts)
    dinv_kernel<<<(M + T - 1) / T, T>>>(M);
    // 4: layer-1 GEMM (only needs x, W1, dinv) — lands in the ncu capture slot
    gcn_gemm_kernel<128, false><<<(M + 127) / 128, T>>>(x, W1, b1, nullptr, M);
    // 5-8: CSR offsets + fill
    scan_a_kernel<<<NB, 256>>>(M);
    scan_b_kernel<<<1, 1024>>>(NB, M);
    scan_c_kernel<<<NB, 256>>>(M);
    fill_kernel<<<(E + T - 1) / T, T>>>(ei, E);
    // 9: layer-1 aggregate
    gather_kernel<false><<<(int)(((long long)M * 16 + T - 1) / T), T>>>(nullptr, M);
    // 10-11: layer 2
    gcn_gemm_kernel<64, true><<<(M + 127) / 128, T>>>(nullptr, W2, b2, out, M);
    gather_kernel<true><<<(int)(((long long)M * 16 + T - 1) / T), T>>>(out, M);
}

// round 7
// speedup vs baseline: 2.2847x; 1.0130x over previous
#include <cuda_runtime.h>
#include <cuda_bf16.h>

#define MAXN 100000
#define MAXE 1700000
#define FDIM 64
#define NB_MAX ((MAXN + 255) / 256)   // 391

// Scratch — __device__ globals, referenced DIRECTLY in kernels.
__device__ int   g_is64;            // 1 if edge_index is int64, 0 if int32
__device__ int   g_cnt[MAXN];
__device__ int   g_off[MAXN + 1];
__device__ int   g_cursor[MAXN];
__device__ int   g_srcs[MAXE];
__device__ int   g_blockoff[NB_MAX];
__device__ float g_dinv[MAXN];
__device__ float g_Hs1[(size_t)MAXN * FDIM];   // dinv-scaled hidden, layer 1
__device__ float g_agg1[(size_t)MAXN * FDIM];
__device__ float g_Hs2[(size_t)MAXN * FDIM];   // dinv-scaled hidden, layer 2

// ---------------------------------------------------------------------------
// init: detect edge dtype (thread 0) + zero g_cnt.
// ---------------------------------------------------------------------------
__global__ void init_kernel(const unsigned int* __restrict__ raw, int M, int E) {
    int i = blockIdx.x * blockDim.x + threadIdx.x;
    if (i < M) g_cnt[i] = 0;
    if (i == 0) {
        int nz = 0;
        int lim = E < 64 ? E : 64;
        for (int k = 0; k < lim; k++)
            if (raw[2 * k + 1] != 0u) nz++;
        g_is64 = (nz == 0) ? 1 : 0;
    }
}

__device__ __forceinline__ int edge_at(const void* ei, int is64, size_t idx) {
    if (is64) return (int)((const long long*)ei)[idx];
    return ((const int*)ei)[idx];
}

__global__ void count_kernel(const void* __restrict__ ei, int E) {
    int e = blockIdx.x * blockDim.x + threadIdx.x;
    if (e < E) {
        int is64 = g_is64;
        int c = edge_at(ei, is64, (size_t)E + e);  // target node
        atomicAdd(&g_cnt[c], 1);
    }
}

// --- 3-phase grid-wide exclusive scan of g_cnt -> g_off (A also emits dinv) ---
__global__ void scan_a_kernel(int M) {
    __shared__ int sh[256];
    int tid = threadIdx.x;
    int i = blockIdx.x * 256 + tid;
    int v = (i < M) ? g_cnt[i] : 0;
    if (i < M) g_dinv[i] = rsqrtf((float)(v + 1));
    sh[tid] = v;
    __syncthreads();
#pragma unroll
    for (int d = 128; d > 0; d >>= 1) {
        if (tid < d) sh[tid] += sh[tid + d];
        __syncthreads();
    }
    if (tid == 0) g_blockoff[blockIdx.x] = sh[0];
}

__global__ void scan_b_kernel(int NB, int M) {
    __shared__ int sh[1024];
    int tid = threadIdx.x;
    int v = (tid < NB) ? g_blockoff[tid] : 0;
    sh[tid] = v;
    __syncthreads();
    for (int d = 1; d < 1024; d <<= 1) {
        int t = (tid >= d) ? sh[tid - d] : 0;
        __syncthreads();
        sh[tid] += t;
        __syncthreads();
    }
    if (tid < NB) g_blockoff[tid] = sh[tid] - v;   // exclusive
    if (tid == NB - 1) g_off[M] = sh[tid];
}

__global__ void scan_c_kernel(int M) {
    __shared__ int sh[256];
    int tid = threadIdx.x;
    int i = blockIdx.x * 256 + tid;
    int v = (i < M) ? g_cnt[i] : 0;
    sh[tid] = v;
    __syncthreads();
    for (int d = 1; d < 256; d <<= 1) {
        int t = (tid >= d) ? sh[tid - d] : 0;
        __syncthreads();
        sh[tid] += t;
        __syncthreads();
    }
    if (i < M) {
        int pos = g_blockoff[blockIdx.x] + sh[tid] - v;  // exclusive
        g_off[i] = pos;
        g_cursor[i] = pos;
    }
}

__global__ void fill_kernel(const void* __restrict__ ei, int E) {
    int e = blockIdx.x * blockDim.x + threadIdx.x;
    if (e < E) {
        int is64 = g_is64;
        int r = edge_at(ei, is64, (size_t)e);           // source
        int c = edge_at(ei, is64, (size_t)E + e);       // target
        int pos = atomicAdd(&g_cursor[c], 1);
        g_srcs[pos] = r;
    }
}

// ---------------------------------------------------------------------------
// GEMM: Hs = dinv .* (act(X) @ W).  (self-loop/bias handled in gather)
// 256 threads -> 64x64 tile; thread = 4x4; k-major transposed X tile.
// __launch_bounds__(256,4): ~48 regs -> 4 CTAs/SM -> 50% occupancy.
// ---------------------------------------------------------------------------
template <int K, bool LAYER2>
__global__ void __launch_bounds__(256, 4)
gcn_gemm_kernel(const float* __restrict__ Xin,
                const float* __restrict__ W,
                float* __restrict__ Hs_out_unused, int M) {
    const float* X  = LAYER2 ? g_agg1 : Xin;
    float*       Hs = LAYER2 ? g_Hs2  : g_Hs1;

    constexpr int KT = 64;
    __shared__ float Ws[KT][64];         // 16 KB
    __shared__ float xsT[KT][68];        // 17.4 KB, k-major (68*4 = 272 = 17*16 OK)

    const int tid = threadIdx.x;
    const int tx = tid & 15;             // cols tx*4..+3
    const int ty = tid >> 4;             // rows ty*4..+3
    const int row0 = blockIdx.x * 64;

    float acc[4][4];
#pragma unroll
    for (int r = 0; r < 4; r++)
#pragma unroll
        for (int c = 0; c < 4; c++) acc[r][c] = 0.0f;

    for (int k0 = 0; k0 < K; k0 += KT) {
        // W tile: 64x64 = 1024 float4, 4 per thread
#pragma unroll
        for (int i = tid; i < KT * 16; i += 256) {
            int kk = i >> 4, cc = (i & 15) * 4;
            *(float4*)&Ws[kk][cc] = *(const float4*)&W[(size_t)(k0 + kk) * 64 + cc];
        }
        // X tile, transposed store: 64 rows x 64 k = 1024 float4, 4 per thread
#pragma unroll
        for (int i = tid; i < 64 * 16; i += 256) {
            int r = i >> 4;              // row 0..63
            int j = i & 15;              // k group
            int row = row0 + r;
            float4 v = make_float4(0.f, 0.f, 0.f, 0.f);
            if (row < M)
                v = *(const float4*)&X[(size_t)row * K + k0 + j * 4];
            if (LAYER2) {
                v.x = fmaxf(v.x, 0.f); v.y = fmaxf(v.y, 0.f);
                v.z = fmaxf(v.z, 0.f); v.w = fmaxf(v.w, 0.f);
            }
            xsT[j * 4 + 0][r] = v.x;
            xsT[j * 4 + 1][r] = v.y;
            xsT[j * 4 + 2][r] = v.z;
            xsT[j * 4 + 3][r] = v.w;
        }
        __syncthreads();

#pragma unroll 8
        for (int k = 0; k < KT; k++) {
            float4 w  = *(const float4*)&Ws[k][tx * 4];
            float4 xv = *(const float4*)&xsT[k][ty * 4];
            acc[0][0] += xv.x * w.x; acc[0][1] += xv.x * w.y;
            acc[0][2] += xv.x * w.z; acc[0][3] += xv.x * w.w;
            acc[1][0] += xv.y * w.x; acc[1][1] += xv.y * w.y;
            acc[1][2] += xv.y * w.z; acc[1][3] += xv.y * w.w;
            acc[2][0] += xv.z * w.x; acc[2][1] += xv.z * w.y;
            acc[2][2] += xv.z * w.z; acc[2][3] += xv.z * w.w;
            acc[3][0] += xv.w * w.x; acc[3][1] += xv.w * w.y;
            acc[3][2] += xv.w * w.z; acc[3][3] += xv.w * w.w;
        }
        __syncthreads();
    }

#pragma unroll
    for (int r = 0; r < 4; r++) {
        int row = row0 + ty * 4 + r;
        if (row < M) {
            float d = g_dinv[row];
            float4 h = make_float4(acc[r][0] * d, acc[r][1] * d,
                                   acc[r][2] * d, acc[r][3] * d);
            *(float4*)&Hs[(size_t)row * 64 + tx * 4] = h;
        }
    }
}

// ---------------------------------------------------------------------------
// CSR gather + self-loop + bias:
//   agg[n] = bias + dinv[n] * (Hs[n] + sum_{src in N(n)} Hs[src])
// 16 threads per node, one float4 channel slice each. No atomics.
// ---------------------------------------------------------------------------
template <bool LAYER2>
__global__ void gather_kernel(const float* __restrict__ bias,
                              float* __restrict__ AGGout, int M) {
    const float* Hs  = LAYER2 ? g_Hs2  : g_Hs1;
    float*       agg = LAYER2 ? AGGout : g_agg1;

    long long gid = (long long)blockIdx.x * blockDim.x + threadIdx.x;
    int n = (int)(gid >> 4);
    if (n >= M) return;
    int lane = (int)(gid & 15);

    size_t base = (size_t)n * 64 + lane * 4;
    float4 a = *(const float4*)&Hs[base];   // self term

    int s = g_off[n], e = g_off[n + 1];
#pragma unroll 4
    for (int j = s; j < e; j++) {
        int r = g_srcs[j];
        float4 h = *(const float4*)&Hs[(size_t)r * 64 + lane * 4];
        a.x += h.x; a.y += h.y; a.z += h.z; a.w += h.w;
    }
    float dn = g_dinv[n];
    float4 bv = *(const float4*)&bias[lane * 4];
    float4 o = make_float4(bv.x + dn * a.x, bv.y + dn * a.y,
                           bv.z + dn * a.z, bv.w + dn * a.w);
    *(float4*)&agg[base] = o;
}

// ---------------------------------------------------------------------------
extern "C" void kernel_launch(void* const* d_in, const int* in_sizes, int n_in,
                              void* d_out, int out_size) {
    const float* x  = (const float*)d_in[0];
    const void*  ei = d_in[1];
    const float* W1 = (const float*)d_in[2];
    const float* b1 = (const float*)d_in[3];
    const float* W2 = (const float*)d_in[4];
    const float* b2 = (const float*)d_in[5];
    float*       out = (float*)d_out;

    const int M = in_sizes[0] / 128;   // 100000
    const int E = in_sizes[1] / 2;     // 1600000
    const int NB = (M + 255) / 256;

    const int T = 256;
    // 1: dtype detect + zero counts
    init_kernel<<<(M + T - 1) / T, T>>>((const unsigned int*)ei, M, E);
    // 2: degree counts
    count_kernel<<<(E + T - 1) / T, T>>>(ei, E);
    // 3: scan A (also emits dinv)
    scan_a_kernel<<<NB, 256>>>(M);
    // 4: layer-1 GEMM — ncu capture slot
    gcn_gemm_kernel<128, false><<<(M + 63) / 64, T>>>(x, W1, nullptr, M);
    // 5-7: CSR offsets + fill
    scan_b_kernel<<<1, 1024>>>(NB, M);
    scan_c_kernel<<<NB, 256>>>(M);
    fill_kernel<<<(E + T - 1) / T, T>>>(ei, E);
    // 8: layer-1 aggregate (writes g_agg1)
    gather_kernel<false><<<(int)(((long long)M * 16 + T - 1) / T), T>>>(b1, nullptr, M);
    // 9-10: layer 2 (gather writes d_out)
    gcn_gemm_kernel<64, true><<<(M + 63) / 64, T>>>(nullptr, W2, nullptr, M);
    gather_kernel<true><<<(int)(((long long)M * 16 + T - 1) / T), T>>>(b2, out, M);
}